// round 7
// baseline (speedup 1.0000x reference)
#include <cuda_runtime.h>
#include <cuda_bf16.h>
#include <mma.h>
#include <math.h>
#include <stdint.h>

using namespace nvcuda;

#define BATCH 8
#define TSTEPS 2048
#define DIM 1024
#define MM (BATCH * TSTEPS)   // 16384 rows
#define NN 1024
#define KK 1024
#define EPS 1e-6f

// ---------------- device-global scratch (allocation-free) -------------------
__device__ float         g_wx [(size_t)MM * NN];   // fp32 scan input
__device__ __nv_bfloat16 g_xh [(size_t)MM * KK], g_xl [(size_t)MM * KK];   // split(x)
__device__ __nv_bfloat16 g_aph[(size_t)MM * KK], g_apl[(size_t)MM * KK];   // split(xp)
__device__ __nv_bfloat16 g_oh [(size_t)MM * KK], g_ol [(size_t)MM * KK];   // split(outs)
__device__ __nv_bfloat16 g_wih[(size_t)NN * KK], g_wil[(size_t)NN * KK];
__device__ __nv_bfloat16 g_wch[(size_t)NN * KK], g_wcl[(size_t)NN * KK];
__device__ __nv_bfloat16 g_woh[(size_t)NN * KK], g_wol[(size_t)NN * KK];

// ---------------- fp32 -> bf16 hi/lo split (one-time) -----------------------
__global__ void split_fp32(const float* __restrict__ s,
                           __nv_bfloat16* __restrict__ hi,
                           __nv_bfloat16* __restrict__ lo, int n8)
{
    int i = blockIdx.x * blockDim.x + threadIdx.x;
    if (i >= n8) return;
    const float4* p = (const float4*)s + (size_t)i * 2;
    float4 a = p[0], b = p[1];
    float v[8] = {a.x, a.y, a.z, a.w, b.x, b.y, b.z, b.w};
    __align__(16) __nv_bfloat16 h[8], l[8];
#pragma unroll
    for (int q = 0; q < 8; q++) {
        h[q] = __float2bfloat16(v[q]);
        l[q] = __float2bfloat16(v[q] - __bfloat162float(h[q]));
    }
    *(uint4*)(hi + (size_t)i * 8) = *(uint4*)h;
    *(uint4*)(lo + (size_t)i * 8) = *(uint4*)l;
}

// ---------------- cp.async helpers ------------------------------------------
__device__ __forceinline__ void cp_async_16(void* smem, const void* gmem)
{
    uint32_t s = (uint32_t)__cvta_generic_to_shared(smem);
    asm volatile("cp.async.ca.shared.global [%0], [%1], 16;\n" :: "r"(s), "l"(gmem));
}
__device__ __forceinline__ void cp_commit()
{
    asm volatile("cp.async.commit_group;\n" ::: "memory");
}
template <int N>
__device__ __forceinline__ void cp_wait()
{
    asm volatile("cp.async.wait_group %0;\n" :: "n"(N) : "memory");
}

// ---------------- pipelined bf16 3-pass GEMM --------------------------------
#define BM 128
#define BN 128
#define BK 32
#define LDT 40                       // smem row stride in bf16 elems (80B)
#define QUAD (BM * LDT * 2)          // 10240 B per quadrant tile
#define STAGE_BYTES (4 * QUAD)       // 40960 B
#define STAGES 4
#define GEMM_SMEM (STAGES * STAGE_BYTES)   // 163840 B

__device__ __forceinline__ void load_quad(const __nv_bfloat16* __restrict__ gplane,
                                          int grow0, int k0, char* sq, int tid)
{
#pragma unroll
    for (int i = 0; i < 2; i++) {
        int c   = tid + i * 256;       // 0..511
        int row = c >> 2;              // 0..127
        int cb  = c & 3;               // 16B chunk within 64B row
        const __nv_bfloat16* g = gplane + (size_t)(grow0 + row) * KK + k0 + cb * 8;
        cp_async_16(sq + row * (LDT * 2) + cb * 16, g);
    }
}

template <int MODE>
__global__ __launch_bounds__(256, 1)
void gemm_bf16(const __nv_bfloat16* __restrict__ Ah_, const __nv_bfloat16* __restrict__ Al_,
               const __nv_bfloat16* __restrict__ Bh_, const __nv_bfloat16* __restrict__ Bl_,
               const float* __restrict__ bias, const float* __restrict__ log_alpha,
               float* __restrict__ Cf,
               __nv_bfloat16* __restrict__ Ch, __nv_bfloat16* __restrict__ Cl)
{
    extern __shared__ __align__(16) char dsm[];

    const int tid  = threadIdx.x;
    const int wid  = tid >> 5;
    const int lane = tid & 31;
    const int bm   = blockIdx.y * BM;
    const int bn   = blockIdx.x * BN;

    const int wm = wid & 1;   // 64-row slab
    const int wn = wid >> 1;  // 32-col slab

    wmma::fragment<wmma::accumulator, 16, 16, 16, float> acc[4][2];
#pragma unroll
    for (int i = 0; i < 4; i++)
#pragma unroll
        for (int j = 0; j < 2; j++) wmma::fill_fragment(acc[i][j], 0.0f);

    const int NT = KK / BK;   // 32 tiles

    // prologue: fill stages 0..STAGES-2
#pragma unroll
    for (int s = 0; s < STAGES - 1; s++) {
        char* p = dsm + s * STAGE_BYTES;
        load_quad(Ah_, bm, s * BK, p,            tid);
        load_quad(Al_, bm, s * BK, p + QUAD,     tid);
        load_quad(Bh_, bn, s * BK, p + 2 * QUAD, tid);
        load_quad(Bl_, bn, s * BK, p + 3 * QUAD, tid);
        cp_commit();
    }

    for (int t = 0; t < NT; t++) {
        cp_wait<STAGES - 2>();
        __syncthreads();

        // refill freed stage FIRST — maximizes load/compute overlap
        if (t + STAGES - 1 < NT) {
            const int tn = t + STAGES - 1;
            char* pn = dsm + (tn % STAGES) * STAGE_BYTES;
            load_quad(Ah_, bm, tn * BK, pn,            tid);
            load_quad(Al_, bm, tn * BK, pn + QUAD,     tid);
            load_quad(Bh_, bn, tn * BK, pn + 2 * QUAD, tid);
            load_quad(Bl_, bn, tn * BK, pn + 3 * QUAD, tid);
        }
        cp_commit();

        char* p = dsm + (t % STAGES) * STAGE_BYTES;
        const __nv_bfloat16* Ah = (const __nv_bfloat16*)p;
        const __nv_bfloat16* Al = (const __nv_bfloat16*)(p + QUAD);
        const __nv_bfloat16* Bh = (const __nv_bfloat16*)(p + 2 * QUAD);
        const __nv_bfloat16* Bl = (const __nv_bfloat16*)(p + 3 * QUAD);

#pragma unroll
        for (int ks = 0; ks < BK; ks += 16) {
            wmma::fragment<wmma::matrix_a, 16, 16, 16, __nv_bfloat16, wmma::row_major> fah[4], fal[4];
            wmma::fragment<wmma::matrix_b, 16, 16, 16, __nv_bfloat16, wmma::col_major> fbh[2], fbl[2];
#pragma unroll
            for (int i = 0; i < 4; i++) {
                const int row = wm * 64 + i * 16;
                wmma::load_matrix_sync(fah[i], Ah + row * LDT + ks, LDT);
                wmma::load_matrix_sync(fal[i], Al + row * LDT + ks, LDT);
            }
#pragma unroll
            for (int j = 0; j < 2; j++) {
                const int col = wn * 32 + j * 16;
                wmma::load_matrix_sync(fbh[j], Bh + col * LDT + ks, LDT);
                wmma::load_matrix_sync(fbl[j], Bl + col * LDT + ks, LDT);
            }
#pragma unroll
            for (int i = 0; i < 4; i++)
#pragma unroll
                for (int j = 0; j < 2; j++) {
                    wmma::mma_sync(acc[i][j], fah[i], fbl[j], acc[i][j]);
                    wmma::mma_sync(acc[i][j], fal[i], fbh[j], acc[i][j]);
                    wmma::mma_sync(acc[i][j], fah[i], fbh[j], acc[i][j]);
                }
        }
    }
    __syncthreads();

    // ---- epilogue: per-warp smem staging ----
    float aval = 0.f;
    if (MODE == 1) aval = __expf(log_alpha[0]);
    float* stage = (float*)dsm + wid * 256;   // 16x16 fp32 per warp

    const int r  = lane >> 1;
    const int c0 = (lane & 1) * 8;
#pragma unroll
    for (int i = 0; i < 4; i++) {
#pragma unroll
        for (int j = 0; j < 2; j++) {
            wmma::store_matrix_sync(stage, acc[i][j], 16, wmma::mem_row_major);
            __syncwarp();
            const int grow = bm + wm * 64 + i * 16 + r;
            const int gcol = bn + wn * 32 + j * 16 + c0;
            float v[8];
            *(float4*)&v[0] = *(float4*)&stage[r * 16 + c0];
            *(float4*)&v[4] = *(float4*)&stage[r * 16 + c0 + 4];

            if (MODE == 0) {
                __align__(16) __nv_bfloat16 h8[8], l8[8];
#pragma unroll
                for (int q = 0; q < 8; q++) {
                    float t = v[q];
                    t = t * __fdividef(1.f, 1.f + __expf(-t));     // silu
                    h8[q] = __float2bfloat16(t);
                    l8[q] = __float2bfloat16(t - __bfloat162float(h8[q]));
                }
                *(uint4*)(Ch + (size_t)grow * NN + gcol) = *(uint4*)h8;
                *(uint4*)(Cl + (size_t)grow * NN + gcol) = *(uint4*)l8;
            } else {
#pragma unroll
                for (int q = 0; q < 8; q++) {
                    float t = v[q];
                    if (MODE == 1) t = aval * (t + bias[gcol + q]);
                    v[q] = t;
                }
                float* cp = Cf + (size_t)grow * NN + gcol;
                *(float4*)(cp)     = *(float4*)&v[0];
                *(float4*)(cp + 4) = *(float4*)&v[4];
            }
            __syncwarp();
        }
    }
}

// ---------------- sequential scan -------------------------------------------
// Wx pre-scaled by alpha. Output (silu + bf16 split + store) deferred one step
// so it overlaps the next step's shuffle-reduction latency. Prefetch dist 4.
__global__ __launch_bounds__(256, 1)
void scan_kernel(const float* __restrict__ Wx,
                 const float* __restrict__ h0,
                 __nv_bfloat16* __restrict__ oh,
                 __nv_bfloat16* __restrict__ ol,
                 float* __restrict__ h_final)
{
    const int b    = blockIdx.x;
    const int tid  = threadIdx.x;
    const int lane = tid & 31;
    const int warp = tid >> 5;

    __shared__ float red[2][8];

    float4 h = *(const float4*)(h0 + (size_t)b * DIM + tid * 4);

    const float* wxb = Wx + (size_t)b * TSTEPS * DIM;
    __nv_bfloat16* ohb = oh + (size_t)b * TSTEPS * DIM;
    __nv_bfloat16* olb = ol + (size_t)b * TSTEPS * DIM;

    float4 w0 = *(const float4*)(wxb + (size_t)0 * DIM + tid * 4);
    float4 w1 = *(const float4*)(wxb + (size_t)1 * DIM + tid * 4);
    float4 w2 = *(const float4*)(wxb + (size_t)2 * DIM + tid * 4);
    float4 w3 = *(const float4*)(wxb + (size_t)3 * DIM + tid * 4);

    float4 hp = make_float4(0.f, 0.f, 0.f, 0.f);   // deferred h of step t-1

#pragma unroll 2
    for (int t = 0; t < TSTEPS; t++) {
        const int tn = (t + 4 < TSTEPS) ? (t + 4) : (TSTEPS - 1);
        float4 wxn = *(const float4*)(wxb + (size_t)tn * DIM + tid * 4);

        h.x += w0.x; h.y += w0.y; h.z += w0.z; h.w += w0.w;

        float ss = h.x * h.x;
        ss = fmaf(h.y, h.y, ss);
        ss = fmaf(h.z, h.z, ss);
        ss = fmaf(h.w, h.w, ss);

        // ---- deferred output of step t-1: fills the shfl-latency shadow ----
        if (t > 0) {
            float o[4];
            o[0] = hp.x * hp.x * __fdividef(1.f, 1.f + __expf(-hp.x));
            o[1] = hp.y * hp.y * __fdividef(1.f, 1.f + __expf(-hp.y));
            o[2] = hp.z * hp.z * __fdividef(1.f, 1.f + __expf(-hp.z));
            o[3] = hp.w * hp.w * __fdividef(1.f, 1.f + __expf(-hp.w));
            __align__(8) __nv_bfloat16 h4[4], l4[4];
#pragma unroll
            for (int q = 0; q < 4; q++) {
                h4[q] = __float2bfloat16(o[q]);
                l4[q] = __float2bfloat16(o[q] - __bfloat162float(h4[q]));
            }
            *(uint2*)(ohb + (size_t)(t - 1) * DIM + tid * 4) = *(uint2*)h4;
            *(uint2*)(olb + (size_t)(t - 1) * DIM + tid * 4) = *(uint2*)l4;
        }

#pragma unroll
        for (int off = 16; off > 0; off >>= 1)
            ss += __shfl_xor_sync(0xffffffffu, ss, off);
        if (lane == 0) red[t & 1][warp] = ss;
        __syncthreads();

        float tot = (red[t & 1][0] + red[t & 1][1]) + (red[t & 1][2] + red[t & 1][3]);
        tot += (red[t & 1][4] + red[t & 1][5]) + (red[t & 1][6] + red[t & 1][7]);

        const float rstd = rsqrtf(tot * (1.0f / DIM) + EPS);
        h.x *= rstd; h.y *= rstd; h.z *= rstd; h.w *= rstd;

        hp = h;
        w0 = w1; w1 = w2; w2 = w3; w3 = wxn;
    }

    // final deferred output (t = TSTEPS-1)
    {
        float o[4];
        o[0] = hp.x * hp.x * __fdividef(1.f, 1.f + __expf(-hp.x));
        o[1] = hp.y * hp.y * __fdividef(1.f, 1.f + __expf(-hp.y));
        o[2] = hp.z * hp.z * __fdividef(1.f, 1.f + __expf(-hp.z));
        o[3] = hp.w * hp.w * __fdividef(1.f, 1.f + __expf(-hp.w));
        __align__(8) __nv_bfloat16 h4[4], l4[4];
#pragma unroll
        for (int q = 0; q < 4; q++) {
            h4[q] = __float2bfloat16(o[q]);
            l4[q] = __float2bfloat16(o[q] - __bfloat162float(h4[q]));
        }
        *(uint2*)(ohb + (size_t)(TSTEPS - 1) * DIM + tid * 4) = *(uint2*)h4;
        *(uint2*)(olb + (size_t)(TSTEPS - 1) * DIM + tid * 4) = *(uint2*)l4;
    }

    if (h_final)
        *(float4*)(h_final + (size_t)b * DIM + tid * 4) = h;
}

// ---------------------------------------------------------------------------
extern "C" void kernel_launch(void* const* d_in, const int* in_sizes, int n_in,
                              void* d_out, int out_size)
{
    const float* x         = (const float*)d_in[0];
    const float* h0        = (const float*)d_in[1];
    const float* W_in      = (const float*)d_in[2];
    const float* W_cell    = (const float*)d_in[3];
    const float* b_cell    = (const float*)d_in[4];
    const float* log_alpha = (const float*)d_in[5];
    const float* W_out     = (const float*)d_in[6];

    float* y = (float*)d_out;
    float* h_final = nullptr;
    if ((size_t)out_size >= (size_t)MM * DIM + (size_t)BATCH * DIM)
        h_final = y + (size_t)MM * DIM;

    float* wx = nullptr;
    __nv_bfloat16 *xh, *xl, *aph, *apl, *oh, *ol, *wih, *wil, *wch, *wcl, *woh, *wol;
    cudaGetSymbolAddress((void**)&wx,  g_wx);
    cudaGetSymbolAddress((void**)&xh,  g_xh);  cudaGetSymbolAddress((void**)&xl,  g_xl);
    cudaGetSymbolAddress((void**)&aph, g_aph); cudaGetSymbolAddress((void**)&apl, g_apl);
    cudaGetSymbolAddress((void**)&oh,  g_oh);  cudaGetSymbolAddress((void**)&ol,  g_ol);
    cudaGetSymbolAddress((void**)&wih, g_wih); cudaGetSymbolAddress((void**)&wil, g_wil);
    cudaGetSymbolAddress((void**)&wch, g_wch); cudaGetSymbolAddress((void**)&wcl, g_wcl);
    cudaGetSymbolAddress((void**)&woh, g_woh); cudaGetSymbolAddress((void**)&wol, g_wol);

    static bool attr_done = false;
    if (!attr_done) {
        cudaFuncSetAttribute(gemm_bf16<0>, cudaFuncAttributeMaxDynamicSharedMemorySize, GEMM_SMEM);
        cudaFuncSetAttribute(gemm_bf16<1>, cudaFuncAttributeMaxDynamicSharedMemorySize, GEMM_SMEM);
        cudaFuncSetAttribute(gemm_bf16<2>, cudaFuncAttributeMaxDynamicSharedMemorySize, GEMM_SMEM);
        attr_done = true;
    }

    // one-time splits
    {
        int n8 = MM * KK / 8;
        split_fp32<<<(n8 + 255) / 256, 256>>>(x, xh, xl, n8);
        int w8 = NN * KK / 8;
        split_fp32<<<(w8 + 255) / 256, 256>>>(W_in,   wih, wil, w8);
        split_fp32<<<(w8 + 255) / 256, 256>>>(W_cell, wch, wcl, w8);
        split_fp32<<<(w8 + 255) / 256, 256>>>(W_out,  woh, wol, w8);
    }

    dim3 grid(NN / BN, MM / BM);
    dim3 block(256);

    // GEMM1: xp = silu(x @ W_in^T)  -> bf16 hi/lo planes
    gemm_bf16<0><<<grid, block, GEMM_SMEM>>>(xh, xl, wih, wil, nullptr, nullptr,
                                             nullptr, aph, apl);
    // GEMM2: wx = alpha*(xp @ W_cell^T + b_cell) -> fp32
    gemm_bf16<1><<<grid, block, GEMM_SMEM>>>(aph, apl, wch, wcl, b_cell, log_alpha,
                                             wx, nullptr, nullptr);
    // Scan -> outs hi/lo planes + h_final
    scan_kernel<<<BATCH, 256>>>(wx, h0, oh, ol, h_final);
    // GEMM3: y = outs @ W_out^T -> fp32
    gemm_bf16<2><<<grid, block, GEMM_SMEM>>>(oh, ol, woh, wol, nullptr, nullptr,
                                             y, nullptr, nullptr);
}

// round 8
// speedup vs baseline: 1.0020x; 1.0020x over previous
#include <cuda_runtime.h>
#include <cuda_bf16.h>
#include <mma.h>
#include <math.h>
#include <stdint.h>

using namespace nvcuda;

#define BATCH 8
#define TSTEPS 2048
#define DIM 1024
#define MM (BATCH * TSTEPS)   // 16384 rows
#define NN 1024
#define KK 1024
#define EPS 1e-6f

// ---------------- device-global scratch (allocation-free) -------------------
__device__ float         g_wx [(size_t)MM * NN];   // fp32 scan input
__device__ __nv_bfloat16 g_xh [(size_t)MM * KK], g_xl [(size_t)MM * KK];   // split(x)
__device__ __nv_bfloat16 g_aph[(size_t)MM * KK], g_apl[(size_t)MM * KK];   // split(xp)
__device__ __nv_bfloat16 g_oh [(size_t)MM * KK], g_ol [(size_t)MM * KK];   // split(outs)
__device__ __nv_bfloat16 g_wih[(size_t)NN * KK], g_wil[(size_t)NN * KK];
__device__ __nv_bfloat16 g_wch[(size_t)NN * KK], g_wcl[(size_t)NN * KK];
__device__ __nv_bfloat16 g_woh[(size_t)NN * KK], g_wol[(size_t)NN * KK];

// ---------------- fp32 -> bf16 hi/lo split (one-time) -----------------------
__global__ void split_fp32(const float* __restrict__ s,
                           __nv_bfloat16* __restrict__ hi,
                           __nv_bfloat16* __restrict__ lo, int n8)
{
    int i = blockIdx.x * blockDim.x + threadIdx.x;
    if (i >= n8) return;
    const float4* p = (const float4*)s + (size_t)i * 2;
    float4 a = p[0], b = p[1];
    float v[8] = {a.x, a.y, a.z, a.w, b.x, b.y, b.z, b.w};
    __align__(16) __nv_bfloat16 h[8], l[8];
#pragma unroll
    for (int q = 0; q < 8; q++) {
        h[q] = __float2bfloat16(v[q]);
        l[q] = __float2bfloat16(v[q] - __bfloat162float(h[q]));
    }
    *(uint4*)(hi + (size_t)i * 8) = *(uint4*)h;
    *(uint4*)(lo + (size_t)i * 8) = *(uint4*)l;
}

// ---------------- cp.async helpers ------------------------------------------
__device__ __forceinline__ void cp_async_16(void* smem, const void* gmem)
{
    uint32_t s = (uint32_t)__cvta_generic_to_shared(smem);
    asm volatile("cp.async.ca.shared.global [%0], [%1], 16;\n" :: "r"(s), "l"(gmem));
}
__device__ __forceinline__ void cp_commit()
{
    asm volatile("cp.async.commit_group;\n" ::: "memory");
}
template <int N>
__device__ __forceinline__ void cp_wait()
{
    asm volatile("cp.async.wait_group %0;\n" :: "n"(N) : "memory");
}

// ---------------- pipelined bf16 3-pass GEMM --------------------------------
#define BM 128
#define BN 128
#define BK 32
#define LDT 40                       // smem row stride in bf16 elems (80B)
#define QUAD (BM * LDT * 2)          // 10240 B per quadrant tile
#define STAGE_BYTES (4 * QUAD)       // 40960 B
#define STAGES 4
#define GEMM_SMEM (STAGES * STAGE_BYTES)   // 163840 B

__device__ __forceinline__ void load_quad(const __nv_bfloat16* __restrict__ gplane,
                                          int grow0, int k0, char* sq, int tid)
{
#pragma unroll
    for (int i = 0; i < 2; i++) {
        int c   = tid + i * 256;       // 0..511
        int row = c >> 2;              // 0..127
        int cb  = c & 3;               // 16B chunk within 64B row
        const __nv_bfloat16* g = gplane + (size_t)(grow0 + row) * KK + k0 + cb * 8;
        cp_async_16(sq + row * (LDT * 2) + cb * 16, g);
    }
}

template <int MODE>
__global__ __launch_bounds__(256, 1)
void gemm_bf16(const __nv_bfloat16* __restrict__ Ah_, const __nv_bfloat16* __restrict__ Al_,
               const __nv_bfloat16* __restrict__ Bh_, const __nv_bfloat16* __restrict__ Bl_,
               const float* __restrict__ bias, const float* __restrict__ log_alpha,
               float* __restrict__ Cf,
               __nv_bfloat16* __restrict__ Ch, __nv_bfloat16* __restrict__ Cl)
{
    extern __shared__ __align__(16) char dsm[];

    const int tid  = threadIdx.x;
    const int wid  = tid >> 5;
    const int lane = tid & 31;
    const int bm   = blockIdx.y * BM;
    const int bn   = blockIdx.x * BN;

    const int wm = wid & 1;   // 64-row slab
    const int wn = wid >> 1;  // 32-col slab

    wmma::fragment<wmma::accumulator, 16, 16, 16, float> acc[4][2];
#pragma unroll
    for (int i = 0; i < 4; i++)
#pragma unroll
        for (int j = 0; j < 2; j++) wmma::fill_fragment(acc[i][j], 0.0f);

    const int NT = KK / BK;   // 32 tiles

    // prologue: fill stages 0..STAGES-2
#pragma unroll
    for (int s = 0; s < STAGES - 1; s++) {
        char* p = dsm + s * STAGE_BYTES;
        load_quad(Ah_, bm, s * BK, p,            tid);
        load_quad(Al_, bm, s * BK, p + QUAD,     tid);
        load_quad(Bh_, bn, s * BK, p + 2 * QUAD, tid);
        load_quad(Bl_, bn, s * BK, p + 3 * QUAD, tid);
        cp_commit();
    }

    for (int t = 0; t < NT; t++) {
        cp_wait<STAGES - 2>();
        __syncthreads();

        // refill freed stage FIRST — maximizes load/compute overlap
        if (t + STAGES - 1 < NT) {
            const int tn = t + STAGES - 1;
            char* pn = dsm + (tn % STAGES) * STAGE_BYTES;
            load_quad(Ah_, bm, tn * BK, pn,            tid);
            load_quad(Al_, bm, tn * BK, pn + QUAD,     tid);
            load_quad(Bh_, bn, tn * BK, pn + 2 * QUAD, tid);
            load_quad(Bl_, bn, tn * BK, pn + 3 * QUAD, tid);
        }
        cp_commit();

        char* p = dsm + (t % STAGES) * STAGE_BYTES;
        const __nv_bfloat16* Ah = (const __nv_bfloat16*)p;
        const __nv_bfloat16* Al = (const __nv_bfloat16*)(p + QUAD);
        const __nv_bfloat16* Bh = (const __nv_bfloat16*)(p + 2 * QUAD);
        const __nv_bfloat16* Bl = (const __nv_bfloat16*)(p + 3 * QUAD);

#pragma unroll
        for (int ks = 0; ks < BK; ks += 16) {
            wmma::fragment<wmma::matrix_a, 16, 16, 16, __nv_bfloat16, wmma::row_major> fah[4], fal[4];
            wmma::fragment<wmma::matrix_b, 16, 16, 16, __nv_bfloat16, wmma::col_major> fbh[2], fbl[2];
#pragma unroll
            for (int i = 0; i < 4; i++) {
                const int row = wm * 64 + i * 16;
                wmma::load_matrix_sync(fah[i], Ah + row * LDT + ks, LDT);
                wmma::load_matrix_sync(fal[i], Al + row * LDT + ks, LDT);
            }
#pragma unroll
            for (int j = 0; j < 2; j++) {
                const int col = wn * 32 + j * 16;
                wmma::load_matrix_sync(fbh[j], Bh + col * LDT + ks, LDT);
                wmma::load_matrix_sync(fbl[j], Bl + col * LDT + ks, LDT);
            }
#pragma unroll
            for (int i = 0; i < 4; i++)
#pragma unroll
                for (int j = 0; j < 2; j++) {
                    wmma::mma_sync(acc[i][j], fah[i], fbl[j], acc[i][j]);
                    wmma::mma_sync(acc[i][j], fal[i], fbh[j], acc[i][j]);
                    wmma::mma_sync(acc[i][j], fah[i], fbh[j], acc[i][j]);
                }
        }
    }
    __syncthreads();

    // ---- epilogue: per-warp smem staging ----
    float aval = 0.f;
    if (MODE == 1) aval = __expf(log_alpha[0]);
    float* stage = (float*)dsm + wid * 256;   // 16x16 fp32 per warp

    const int r  = lane >> 1;
    const int c0 = (lane & 1) * 8;
#pragma unroll
    for (int i = 0; i < 4; i++) {
#pragma unroll
        for (int j = 0; j < 2; j++) {
            wmma::store_matrix_sync(stage, acc[i][j], 16, wmma::mem_row_major);
            __syncwarp();
            const int grow = bm + wm * 64 + i * 16 + r;
            const int gcol = bn + wn * 32 + j * 16 + c0;
            float v[8];
            *(float4*)&v[0] = *(float4*)&stage[r * 16 + c0];
            *(float4*)&v[4] = *(float4*)&stage[r * 16 + c0 + 4];

            if (MODE == 0) {
                __align__(16) __nv_bfloat16 h8[8], l8[8];
#pragma unroll
                for (int q = 0; q < 8; q++) {
                    float t = v[q];
                    t = t * __fdividef(1.f, 1.f + __expf(-t));     // silu
                    h8[q] = __float2bfloat16(t);
                    l8[q] = __float2bfloat16(t - __bfloat162float(h8[q]));
                }
                *(uint4*)(Ch + (size_t)grow * NN + gcol) = *(uint4*)h8;
                *(uint4*)(Cl + (size_t)grow * NN + gcol) = *(uint4*)l8;
            } else {
#pragma unroll
                for (int q = 0; q < 8; q++) {
                    float t = v[q];
                    if (MODE == 1) t = aval * (t + bias[gcol + q]);
                    v[q] = t;
                }
                float* cp = Cf + (size_t)grow * NN + gcol;
                *(float4*)(cp)     = *(float4*)&v[0];
                *(float4*)(cp + 4) = *(float4*)&v[4];
            }
            __syncwarp();
        }
    }
}

// ---------------- sequential scan -------------------------------------------
// Wx pre-scaled by alpha. Output (silu + bf16 split + store) deferred one step
// so it overlaps the next step's shuffle-reduction latency. Prefetch dist 4.
__global__ __launch_bounds__(256, 1)
void scan_kernel(const float* __restrict__ Wx,
                 const float* __restrict__ h0,
                 __nv_bfloat16* __restrict__ oh,
                 __nv_bfloat16* __restrict__ ol,
                 float* __restrict__ h_final)
{
    const int b    = blockIdx.x;
    const int tid  = threadIdx.x;
    const int lane = tid & 31;
    const int warp = tid >> 5;

    __shared__ float red[2][8];

    float4 h = *(const float4*)(h0 + (size_t)b * DIM + tid * 4);

    const float* wxb = Wx + (size_t)b * TSTEPS * DIM;
    __nv_bfloat16* ohb = oh + (size_t)b * TSTEPS * DIM;
    __nv_bfloat16* olb = ol + (size_t)b * TSTEPS * DIM;

    float4 w0 = *(const float4*)(wxb + (size_t)0 * DIM + tid * 4);
    float4 w1 = *(const float4*)(wxb + (size_t)1 * DIM + tid * 4);
    float4 w2 = *(const float4*)(wxb + (size_t)2 * DIM + tid * 4);
    float4 w3 = *(const float4*)(wxb + (size_t)3 * DIM + tid * 4);

    float4 hp = make_float4(0.f, 0.f, 0.f, 0.f);   // deferred h of step t-1

#pragma unroll 2
    for (int t = 0; t < TSTEPS; t++) {
        const int tn = (t + 4 < TSTEPS) ? (t + 4) : (TSTEPS - 1);
        float4 wxn = *(const float4*)(wxb + (size_t)tn * DIM + tid * 4);

        h.x += w0.x; h.y += w0.y; h.z += w0.z; h.w += w0.w;

        float ss = h.x * h.x;
        ss = fmaf(h.y, h.y, ss);
        ss = fmaf(h.z, h.z, ss);
        ss = fmaf(h.w, h.w, ss);

        // ---- deferred output of step t-1: fills the shfl-latency shadow ----
        if (t > 0) {
            float o[4];
            o[0] = hp.x * hp.x * __fdividef(1.f, 1.f + __expf(-hp.x));
            o[1] = hp.y * hp.y * __fdividef(1.f, 1.f + __expf(-hp.y));
            o[2] = hp.z * hp.z * __fdividef(1.f, 1.f + __expf(-hp.z));
            o[3] = hp.w * hp.w * __fdividef(1.f, 1.f + __expf(-hp.w));
            __align__(8) __nv_bfloat16 h4[4], l4[4];
#pragma unroll
            for (int q = 0; q < 4; q++) {
                h4[q] = __float2bfloat16(o[q]);
                l4[q] = __float2bfloat16(o[q] - __bfloat162float(h4[q]));
            }
            *(uint2*)(ohb + (size_t)(t - 1) * DIM + tid * 4) = *(uint2*)h4;
            *(uint2*)(olb + (size_t)(t - 1) * DIM + tid * 4) = *(uint2*)l4;
        }

#pragma unroll
        for (int off = 16; off > 0; off >>= 1)
            ss += __shfl_xor_sync(0xffffffffu, ss, off);
        if (lane == 0) red[t & 1][warp] = ss;
        __syncthreads();

        float tot = (red[t & 1][0] + red[t & 1][1]) + (red[t & 1][2] + red[t & 1][3]);
        tot += (red[t & 1][4] + red[t & 1][5]) + (red[t & 1][6] + red[t & 1][7]);

        const float rstd = rsqrtf(tot * (1.0f / DIM) + EPS);
        h.x *= rstd; h.y *= rstd; h.z *= rstd; h.w *= rstd;

        hp = h;
        w0 = w1; w1 = w2; w2 = w3; w3 = wxn;
    }

    // final deferred output (t = TSTEPS-1)
    {
        float o[4];
        o[0] = hp.x * hp.x * __fdividef(1.f, 1.f + __expf(-hp.x));
        o[1] = hp.y * hp.y * __fdividef(1.f, 1.f + __expf(-hp.y));
        o[2] = hp.z * hp.z * __fdividef(1.f, 1.f + __expf(-hp.z));
        o[3] = hp.w * hp.w * __fdividef(1.f, 1.f + __expf(-hp.w));
        __align__(8) __nv_bfloat16 h4[4], l4[4];
#pragma unroll
        for (int q = 0; q < 4; q++) {
            h4[q] = __float2bfloat16(o[q]);
            l4[q] = __float2bfloat16(o[q] - __bfloat162float(h4[q]));
        }
        *(uint2*)(ohb + (size_t)(TSTEPS - 1) * DIM + tid * 4) = *(uint2*)h4;
        *(uint2*)(olb + (size_t)(TSTEPS - 1) * DIM + tid * 4) = *(uint2*)l4;
    }

    if (h_final)
        *(float4*)(h_final + (size_t)b * DIM + tid * 4) = h;
}

// ---------------------------------------------------------------------------
extern "C" void kernel_launch(void* const* d_in, const int* in_sizes, int n_in,
                              void* d_out, int out_size)
{
    const float* x         = (const float*)d_in[0];
    const float* h0        = (const float*)d_in[1];
    const float* W_in      = (const float*)d_in[2];
    const float* W_cell    = (const float*)d_in[3];
    const float* b_cell    = (const float*)d_in[4];
    const float* log_alpha = (const float*)d_in[5];
    const float* W_out     = (const float*)d_in[6];

    float* y = (float*)d_out;
    float* h_final = nullptr;
    if ((size_t)out_size >= (size_t)MM * DIM + (size_t)BATCH * DIM)
        h_final = y + (size_t)MM * DIM;

    float* wx = nullptr;
    __nv_bfloat16 *xh, *xl, *aph, *apl, *oh, *ol, *wih, *wil, *wch, *wcl, *woh, *wol;
    cudaGetSymbolAddress((void**)&wx,  g_wx);
    cudaGetSymbolAddress((void**)&xh,  g_xh);  cudaGetSymbolAddress((void**)&xl,  g_xl);
    cudaGetSymbolAddress((void**)&aph, g_aph); cudaGetSymbolAddress((void**)&apl, g_apl);
    cudaGetSymbolAddress((void**)&oh,  g_oh);  cudaGetSymbolAddress((void**)&ol,  g_ol);
    cudaGetSymbolAddress((void**)&wih, g_wih); cudaGetSymbolAddress((void**)&wil, g_wil);
    cudaGetSymbolAddress((void**)&wch, g_wch); cudaGetSymbolAddress((void**)&wcl, g_wcl);
    cudaGetSymbolAddress((void**)&woh, g_woh); cudaGetSymbolAddress((void**)&wol, g_wol);

    static bool attr_done = false;
    if (!attr_done) {
        cudaFuncSetAttribute(gemm_bf16<0>, cudaFuncAttributeMaxDynamicSharedMemorySize, GEMM_SMEM);
        cudaFuncSetAttribute(gemm_bf16<1>, cudaFuncAttributeMaxDynamicSharedMemorySize, GEMM_SMEM);
        cudaFuncSetAttribute(gemm_bf16<2>, cudaFuncAttributeMaxDynamicSharedMemorySize, GEMM_SMEM);
        attr_done = true;
    }

    // one-time splits
    {
        int n8 = MM * KK / 8;
        split_fp32<<<(n8 + 255) / 256, 256>>>(x, xh, xl, n8);
        int w8 = NN * KK / 8;
        split_fp32<<<(w8 + 255) / 256, 256>>>(W_in,   wih, wil, w8);
        split_fp32<<<(w8 + 255) / 256, 256>>>(W_cell, wch, wcl, w8);
        split_fp32<<<(w8 + 255) / 256, 256>>>(W_out,  woh, wol, w8);
    }

    dim3 grid(NN / BN, MM / BM);
    dim3 block(256);

    // GEMM1: xp = silu(x @ W_in^T)  -> bf16 hi/lo planes
    gemm_bf16<0><<<grid, block, GEMM_SMEM>>>(xh, xl, wih, wil, nullptr, nullptr,
                                             nullptr, aph, apl);
    // GEMM2: wx = alpha*(xp @ W_cell^T + b_cell) -> fp32
    gemm_bf16<1><<<grid, block, GEMM_SMEM>>>(aph, apl, wch, wcl, b_cell, log_alpha,
                                             wx, nullptr, nullptr);
    // Scan -> outs hi/lo planes + h_final
    scan_kernel<<<BATCH, 256>>>(wx, h0, oh, ol, h_final);
    // GEMM3: y = outs @ W_out^T -> fp32
    gemm_bf16<2><<<grid, block, GEMM_SMEM>>>(oh, ol, woh, wol, nullptr, nullptr,
                                             y, nullptr, nullptr);
}